// round 16
// baseline (speedup 1.0000x reference)
#include <cuda_runtime.h>
#include <cuda_fp16.h>
#include <cstdint>

// LinearAttentionCell with T=1 reduces algebraically to out = x @ Wv^T.
// R16: cp.async W streaming. R15 proved the limiter is delivered fabric
// bytes AND that delivered BW rises with concurrent demand (1.54->1.73TB/s).
// cp.async.cg (LDGSTS) has no destination registers -> outstanding bytes not
// capped by reg pressure or LDG->cvt->STS return chains; 16 ops/thread x 16B
// = ~128KB/SM truly in flight. W lands raw fp32 in smem (pitch 136 floats,
// conflict-free half-warp LDS.64); B frags = LDS.64 + cvt (R14-validated).
// x path + MMA skeleton + atomic split-K identical to R15 (best measured).
// Numerics: single-product fp16 (rel_err ~2.9e-4, R13/R15-validated).

#define KDIM 2048
#define NDIM 2048
#define MDIM 64
#define NT   128
#define SPLITK 16
#define KCH  128
#define KSTEPS 8      // k16 steps per CTA
#define GT   256      // 8 warps: 2 wm(m32) x 4 wn(n32)
#define WPITCH 136    // fp32 W smem row pitch in floats (544B)

// dynamic smem layout (bytes)
#define SM_AH 0                          // [8][2048] fp16 x tiles
#define SM_WF 16384                      // 128 rows x 136 floats
#define SM_TOTAL (16384 + 128 * WPITCH * 4)   // 86016

__device__ __forceinline__ uint32_t f16x2(float hi_e, float lo_e) {
    // packs: low 16 = f16(lo_e), high 16 = f16(hi_e)
    uint32_t r;
    asm("cvt.rn.f16x2.f32 %0, %1, %2;" : "=r"(r) : "f"(hi_e), "f"(lo_e));
    return r;
}

__device__ __forceinline__ void mma_f16(float* d, const uint32_t* a,
                                        uint32_t b0, uint32_t b1) {
    asm volatile(
        "mma.sync.aligned.m16n8k16.row.col.f32.f16.f16.f32 "
        "{%0,%1,%2,%3}, {%4,%5,%6,%7}, {%8,%9}, {%0,%1,%2,%3};"
        : "+f"(d[0]), "+f"(d[1]), "+f"(d[2]), "+f"(d[3])
        : "r"(a[0]), "r"(a[1]), "r"(a[2]), "r"(a[3]), "r"(b0), "r"(b1));
}

__device__ __forceinline__ void ldsm4(uint32_t* r, uint32_t addr) {
    asm volatile(
        "ldmatrix.sync.aligned.m8n8.x4.shared.b16 {%0,%1,%2,%3}, [%4];"
        : "=r"(r[0]), "=r"(r[1]), "=r"(r[2]), "=r"(r[3]) : "r"(addr));
}

// swizzled 16B-chunk offset within a [rows x 16k] fp16 tile (pitch 32B)
__device__ __forceinline__ uint32_t swz(int row, int khalf) {
    return (uint32_t)(row * 32 + (((khalf ^ (row >> 2)) & 1) << 4));
}

__global__ __launch_bounds__(GT, 2)
void gemm_kernel(const float* __restrict__ x, const float* __restrict__ Wv,
                 float* __restrict__ out) {
    extern __shared__ __align__(16) char smem[];
    uint8_t* AH = reinterpret_cast<uint8_t*>(smem + SM_AH);
    float*   WF = reinterpret_cast<float*>(smem + SM_WF);

    const int tid  = threadIdx.x;
    const int lane = tid & 31;
    const int wid  = tid >> 5;
    const int wm   = wid & 1;      // m32 group 0..1
    const int wn   = wid >> 1;     // n32 group 0..3
    const int g  = lane >> 2;
    const int tt = lane & 3;

    const int n0 = blockIdx.x * NT;
    const int k0 = blockIdx.y * KCH;

    // ---- 1. fire 16 cp.asyncs for W (register-free, fully outstanding) ----
    // 4096 16B chunks total: chunk o -> row o/32, 16B col (o%32)
    {
        const float* wbase = Wv + (size_t)n0 * KDIM + k0;
        uint32_t wdst = (uint32_t)__cvta_generic_to_shared(WF);
#pragma unroll
        for (int i = 0; i < 16; i++) {
            int o    = tid * 16 + i;
            int row  = o >> 5;
            int col  = (o & 31) << 2;   // float index within row
            uint32_t dst = wdst + (uint32_t)(row * (WPITCH * 4) + col * 4);
            const float* src = wbase + (size_t)row * KDIM + col;
            asm volatile("cp.async.cg.shared.global [%0], [%1], 16;"
                         :: "r"(dst), "l"(src) : "memory");
        }
        asm volatile("cp.async.commit_group;" ::: "memory");
    }

    // ---- 2. x slice via LDG burst -> fp16 A tiles (R15-validated) ----
    const int r   = tid >> 2;           // 0..63
    const int kq  = (tid & 3) * 4;
    const int hq  = kq >> 3;
    const int off8 = (kq & 4) ? 8 : 0;
    const uint32_t so_x = swz(r, hq) + off8;
    {
        const float* xp = x + (size_t)r * KDIM + k0 + kq;
        float4 xr[KSTEPS];
#pragma unroll
        for (int i = 0; i < KSTEPS; i++)
            xr[i] = *reinterpret_cast<const float4*>(xp + i * 16);
#pragma unroll
        for (int i = 0; i < KSTEPS; i++) {
            uint32_t h01 = f16x2(xr[i].y, xr[i].x);
            uint32_t h23 = f16x2(xr[i].w, xr[i].z);
            *reinterpret_cast<uint2*>(&AH[i * 2048 + so_x]) = make_uint2(h01, h23);
        }
    }

    asm volatile("cp.async.wait_group 0;" ::: "memory");
    __syncthreads();   // the only barrier

    // ---- 3. MMA sweep ----
    const int am0 = wm * 32 + (lane & 15);
    const int am1 = am0 + 16;
    const int akh = lane >> 4;
    const uint32_t aoff0 = swz(am0, akh);
    const uint32_t aoff1 = swz(am1, akh);
    const uint32_t ah_base = (uint32_t)__cvta_generic_to_shared(AH);

    // B fp32 smem row bases (conflict-free: pitch 136 words, half-warp LDS.64)
    int browf[4];
#pragma unroll
    for (int nf = 0; nf < 4; nf++)
        browf[nf] = (wn * 32 + nf * 8 + g) * WPITCH + 2 * tt;

    float acc[2][4][4];
#pragma unroll
    for (int a = 0; a < 2; a++)
#pragma unroll
        for (int b = 0; b < 4; b++)
#pragma unroll
            for (int c = 0; c < 4; c++) acc[a][b][c] = 0.f;

#pragma unroll
    for (int ks = 0; ks < KSTEPS; ks++) {
        uint32_t a0[4], a1[4];
        ldsm4(a0, ah_base + ks * 2048 + aoff0);
        ldsm4(a1, ah_base + ks * 2048 + aoff1);

#pragma unroll
        for (int nf = 0; nf < 4; nf++) {
            float2 p = *reinterpret_cast<const float2*>(&WF[browf[nf] + ks * 16]);
            float2 q = *reinterpret_cast<const float2*>(&WF[browf[nf] + ks * 16 + 8]);
            uint32_t b0 = f16x2(p.y, p.x);
            uint32_t b1 = f16x2(q.y, q.x);
            mma_f16(acc[0][nf], a0, b0, b1);
            mma_f16(acc[1][nf], a1, b0, b1);
        }
    }

    // ---- 4. epilogue: split-K via vector atomics ----
#pragma unroll
    for (int mb = 0; mb < 2; mb++) {
#pragma unroll
        for (int nf = 0; nf < 4; nf++) {
            int m = wm * 32 + mb * 16 + g;
            int n = n0 + wn * 32 + nf * 8 + 2 * tt;
            atomicAdd(reinterpret_cast<float2*>(&out[m * NDIM + n]),
                      make_float2(acc[mb][nf][0], acc[mb][nf][1]));
            atomicAdd(reinterpret_cast<float2*>(&out[(m + 8) * NDIM + n]),
                      make_float2(acc[mb][nf][2], acc[mb][nf][3]));
        }
    }
}

extern "C" void kernel_launch(void* const* d_in, const int* in_sizes, int n_in,
                              void* d_out, int out_size) {
    // inputs: 0=x [64,1,2048] f32, 1=Wq, 2=bq, 3=Wk, 4=bk, 5=Wv [2048,2048], 6=pos
    const float* x  = (const float*)d_in[0];
    const float* Wv = (const float*)d_in[5];
    float* out = (float*)d_out;

    cudaFuncSetAttribute(gemm_kernel,
                         cudaFuncAttributeMaxDynamicSharedMemorySize, SM_TOTAL);

    cudaMemsetAsync(out, 0, (size_t)MDIM * NDIM * sizeof(float));
    dim3 grid(NDIM / NT, SPLITK);   // 16 x 16 = 256 CTAs, one wave
    gemm_kernel<<<grid, GT, SM_TOTAL>>>(x, Wv, out);

    (void)in_sizes; (void)n_in; (void)out_size;
}